// round 2
// baseline (speedup 1.0000x reference)
#include <cuda_runtime.h>

// Problem constants
#define NB   16
#define NCIN 128
#define NCOUT 128
#define NHW  128          // H = W = 128
#define NPIX 16384        // 128*128
#define NK   64           // kernel_num
#define KCOLS 294912      // COUT*CIN*3*3*2 = columns of dft_weight viewed [64, KCOLS]
#define KSIZE 1152        // CIN*9, GEMM K of the conv

// ---------------- scratch (static device globals; no allocations) ------------
__device__ float g_pooled[NB * NCIN];            // [16,128]
__device__ float g_att[NB * NK];                 // [16,64]
__device__ float g_agg[(size_t)NB * KCOLS];      // [16,294912]  (18.9 MB)
__device__ float g_kern[(size_t)NB * NCOUT * KSIZE]; // [16,128,1152] (9.4 MB)

// ---------------- 1) global average pool over H,W ---------------------------
// grid = B*CIN blocks, 256 threads; each block reduces one (b,c) plane.
__global__ void pool_kernel(const float* __restrict__ x) {
    int bc = blockIdx.x;
    const float4* p = (const float4*)(x + (size_t)bc * NPIX);
    float s = 0.f;
    #pragma unroll
    for (int i = 0; i < 16; i++) {
        float4 v = p[threadIdx.x + i * 256];
        s += v.x + v.y + v.z + v.w;
    }
    __shared__ float sd[256];
    sd[threadIdx.x] = s;
    __syncthreads();
    for (int off = 128; off > 0; off >>= 1) {
        if (threadIdx.x < off) sd[threadIdx.x] += sd[threadIdx.x + off];
        __syncthreads();
    }
    if (threadIdx.x == 0) g_pooled[bc] = sd[0] * (1.f / (float)NPIX);
}

// ---------------- 2) attention: sigmoid(pooled @ ksm^T) -> softmax ----------
// one block of 1024 threads: tid = b*64 + k
__global__ void att_kernel(const float* __restrict__ ksm_w) {
    int tid = threadIdx.x;
    int b = tid >> 6;
    int k = tid & 63;
    float s = 0.f;
    #pragma unroll 8
    for (int c = 0; c < NCIN; c++)
        s += g_pooled[b * NCIN + c] * ksm_w[k * NCIN + c];
    float sig = 1.f / (1.f + expf(-s));
    __shared__ float sl[1024];
    sl[tid] = sig;
    __syncthreads();
    float mx = -1e30f;
    #pragma unroll 8
    for (int i = 0; i < NK; i++) mx = fmaxf(mx, sl[b * NK + i]);
    float sum = 0.f;
    #pragma unroll 8
    for (int i = 0; i < NK; i++) sum += expf(sl[b * NK + i] - mx);
    g_att[tid] = expf(sig - mx) / sum;
}

// ---------------- 3) aggregate: agg[b,col] = sum_k att[b,k]*dft[k,col] ------
// grid = 288 blocks * 256 threads; each thread handles 4 columns (stride 256),
// 16 batch accumulators each -> 64 FMA per (16 LDS + 4 LDG).
__global__ void __launch_bounds__(256) agg_kernel(const float* __restrict__ dft) {
    __shared__ float s_att[NB * NK];
    int tid = threadIdx.x;
    #pragma unroll
    for (int i = 0; i < 4; i++) s_att[tid + i * 256] = g_att[tid + i * 256];
    __syncthreads();

    int base = blockIdx.x * 1024 + tid;
    float acc[16][4];
    #pragma unroll
    for (int b = 0; b < 16; b++)
        #pragma unroll
        for (int c = 0; c < 4; c++) acc[b][c] = 0.f;

    for (int k = 0; k < NK; k++) {
        const float* row = dft + (size_t)k * KCOLS + base;
        float w0 = row[0];
        float w1 = row[256];
        float w2 = row[512];
        float w3 = row[768];
        #pragma unroll
        for (int b = 0; b < 16; b++) {
            float a = s_att[b * NK + k];
            acc[b][0] = fmaf(a, w0, acc[b][0]);
            acc[b][1] = fmaf(a, w1, acc[b][1]);
            acc[b][2] = fmaf(a, w2, acc[b][2]);
            acc[b][3] = fmaf(a, w3, acc[b][3]);
        }
    }
    #pragma unroll
    for (int b = 0; b < 16; b++)
        #pragma unroll
        for (int c = 0; c < 4; c++)
            g_agg[(size_t)b * KCOLS + base + c * 256] = acc[b][c];
}

// ---------------- 4) 3x3 ortho iFFT (real part) + clip ----------------------
// one thread per (b, oc, ic): reads 18 contiguous floats, writes 9.
__global__ void ifft_kernel() {
    int id = blockIdx.x * 256 + threadIdx.x;   // 0 .. 262143
    int b = id >> 14;
    int oi = id & 16383;
    const float* a = g_agg + (size_t)b * KCOLS + (size_t)oi * 18;
    float re[9], im[9];
    #pragma unroll
    for (int t = 0; t < 9; t++) { re[t] = a[2 * t]; im[t] = a[2 * t + 1]; }

    const float C3[3] = {1.f, -0.5f, -0.5f};
    const float S3[3] = {0.f, 0.86602540378443864676f, -0.86602540378443864676f};

    float* kout = g_kern + (size_t)id * 9;  // == b*COUT*KSIZE + oc*KSIZE + ic*9
    #pragma unroll
    for (int p = 0; p < 3; p++) {
        #pragma unroll
        for (int q = 0; q < 3; q++) {
            float s = 0.f;
            #pragma unroll
            for (int u = 0; u < 3; u++) {
                #pragma unroll
                for (int v = 0; v < 3; v++) {
                    int m = (u * p + v * q) % 3;
                    s += re[u * 3 + v] * C3[m] - im[u * 3 + v] * S3[m];
                }
            }
            s *= (1.f / 3.f);                       // ortho norm: 1/sqrt(9)
            s = fminf(10.f, fmaxf(-10.f, s));        // clip
            kout[p * 3 + q] = s;
        }
    }
}

// ---------------- 5) per-sample conv as implicit GEMM -----------------------
// Per block: batch b = blockIdx.y, image row y = blockIdx.x.
// GEMM tile: M=128 (all out-channels), N=128 (one full image row), K=1152.
// 256 threads, 8x8 micro-tile per thread.
#define BK 8
__global__ void __launch_bounds__(256, 2) conv_kernel(
    const float* __restrict__ x,
    const float* __restrict__ bias,
    const float* __restrict__ fbm,
    float* __restrict__ out) {

    __shared__ float As[BK][132];   // [k][oc], padded to kill STS bank conflicts
    __shared__ float Bs[BK][128];   // [k][pixel]

    int b = blockIdx.y;
    int y = blockIdx.x;
    int tid = threadIdx.x;
    int tx = tid & 15;       // pixel group
    int ty = tid >> 4;       // oc group

    const float* kb = g_kern + (size_t)b * NCOUT * KSIZE;
    const float* xb = x + (size_t)b * NCIN * NPIX;

    float acc[8][8];
    #pragma unroll
    for (int i = 0; i < 8; i++)
        #pragma unroll
        for (int j = 0; j < 8; j++) acc[i][j] = 0.f;

    for (int k0 = 0; k0 < KSIZE; k0 += BK) {
        // A tile: kernels[b][oc][k0..k0+7]
        #pragma unroll
        for (int l = 0; l < 4; l++) {
            int lin = tid + l * 256;
            int row = lin >> 3;
            int kc = lin & 7;
            As[kc][row] = kb[row * KSIZE + k0 + kc];
        }
        // B tile: im2col on the fly (zero-padded)
        #pragma unroll
        for (int l = 0; l < 4; l++) {
            int lin = tid + l * 256;
            int krow = lin >> 7;
            int col = lin & 127;
            int kk = k0 + krow;
            int ic = kk / 9;
            int t = kk - ic * 9;
            int dy = t / 3;
            int dx = t - dy * 3;
            int yy = y + dy - 1;
            int xx = col + dx - 1;
            float v = 0.f;
            if (yy >= 0 && yy < NHW && xx >= 0 && xx < NHW)
                v = xb[(ic * NHW + yy) * NHW + xx];
            Bs[krow][col] = v;
        }
        __syncthreads();

        #pragma unroll
        for (int k = 0; k < BK; k++) {
            float4 a0 = *(const float4*)&As[k][ty * 8];
            float4 a1 = *(const float4*)&As[k][ty * 8 + 4];
            float4 b0 = *(const float4*)&Bs[k][tx * 8];
            float4 b1 = *(const float4*)&Bs[k][tx * 8 + 4];
            float ra[8] = {a0.x, a0.y, a0.z, a0.w, a1.x, a1.y, a1.z, a1.w};
            float rb[8] = {b0.x, b0.y, b0.z, b0.w, b1.x, b1.y, b1.z, b1.w};
            #pragma unroll
            for (int i = 0; i < 8; i++)
                #pragma unroll
                for (int j = 0; j < 8; j++)
                    acc[i][j] = fmaf(ra[i], rb[j], acc[i][j]);
        }
        __syncthreads();
    }

    // epilogue: (conv + bias) * fbm_scale
    #pragma unroll
    for (int i = 0; i < 8; i++) {
        int oc = ty * 8 + i;
        float bi = bias[oc];
        float sc = fbm[oc];
        float* o = out + (((size_t)b * NCOUT + oc) * NHW + y) * NHW + tx * 8;
        float4 v0, v1;
        v0.x = (acc[i][0] + bi) * sc;
        v0.y = (acc[i][1] + bi) * sc;
        v0.z = (acc[i][2] + bi) * sc;
        v0.w = (acc[i][3] + bi) * sc;
        v1.x = (acc[i][4] + bi) * sc;
        v1.y = (acc[i][5] + bi) * sc;
        v1.z = (acc[i][6] + bi) * sc;
        v1.w = (acc[i][7] + bi) * sc;
        *(float4*)&o[0] = v0;
        *(float4*)&o[4] = v1;
    }
}

// ---------------- launch -----------------------------------------------------
extern "C" void kernel_launch(void* const* d_in, const int* in_sizes, int n_in,
                              void* d_out, int out_size) {
    const float* x    = (const float*)d_in[0];   // [16,128,128,128]
    const float* dft  = (const float*)d_in[1];   // [64,128,128,3,3,2]
    const float* ksm  = (const float*)d_in[2];   // [64,128]
    const float* bias = (const float*)d_in[3];   // [128]
    const float* fbm  = (const float*)d_in[4];   // [1,128,1,1]
    float* out = (float*)d_out;                  // [16,128,128,128]

    pool_kernel<<<NB * NCIN, 256>>>(x);
    att_kernel<<<1, 1024>>>(ksm);
    agg_kernel<<<KCOLS / 1024, 256>>>(dft);
    ifft_kernel<<<(NB * NCOUT * NCIN) / 256, 256>>>();
    conv_kernel<<<dim3(NHW, NB), 256>>>(x, bias, fbm, out);
}

// round 5
// speedup vs baseline: 2.5155x; 2.5155x over previous
#include <cuda_runtime.h>
#include <cstdint>

// ---------------- problem constants ----------------
#define NB    16
#define NCIN  128
#define NCOUT 128
#define NHW   128
#define NPIX  16384
#define NK    64
#define KCOLS 294912
#define KSIZE 1152
#define NSTAGE 72           // KSIZE / 16
#define APAD  20
#define BPAD  20
#define ASZ   (128 * APAD)  // floats per A stage
#define BSZ   (128 * BPAD)  // floats per B stage

// ---------------- scratch ----------------
__device__ float g_pooled[NB * NCIN];
__device__ float g_att[NB * NK];
__device__ float g_agg[(size_t)NB * KCOLS];            // 18.9 MB
__device__ float g_kern[(size_t)NB * NCOUT * KSIZE];   // 9.4 MB, tf32-rounded

// ---------------- helpers ----------------
__device__ __forceinline__ uint32_t smem_u32(const void* p) {
    uint32_t a;
    asm("{ .reg .u64 t; cvta.to.shared.u64 t, %1; cvt.u32.u64 %0, t; }" : "=r"(a) : "l"(p));
    return a;
}
#define CP_A16(dst, src) \
    asm volatile("cp.async.ca.shared.global [%0], [%1], 16;" :: "r"(dst), "l"(src) : "memory")
#define CP_COMMIT() asm volatile("cp.async.commit_group;" ::: "memory")
#define CP_WAIT0()  asm volatile("cp.async.wait_group 0;" ::: "memory")

#define LDM(q, addr) \
    asm volatile("ldmatrix.sync.aligned.m8n8.x4.shared.b16 {%0,%1,%2,%3}, [%4];" \
        : "=r"((q)[0]), "=r"((q)[1]), "=r"((q)[2]), "=r"((q)[3]) : "r"(addr))

// A-fragment register order from ldmatrix: q0=a0, q1=a2, q2=a1, q3=a3 -> pass {q0,q2,q1,q3}
#define MMA(C, qa, b0, b1) \
    asm volatile("mma.sync.aligned.m16n8k8.row.col.f32.tf32.tf32.f32 " \
        "{%0,%1,%2,%3},{%4,%5,%6,%7},{%8,%9},{%0,%1,%2,%3};" \
        : "+f"((C)[0]), "+f"((C)[1]), "+f"((C)[2]), "+f"((C)[3]) \
        : "r"((qa)[0]), "r"((qa)[2]), "r"((qa)[1]), "r"((qa)[3]), "r"(b0), "r"(b1))

// ---------------- 1) global average pool ----------------
__global__ void pool_kernel(const float* __restrict__ x) {
    int bc = blockIdx.x;
    const float4* p = (const float4*)(x + (size_t)bc * NPIX);
    float s = 0.f;
    #pragma unroll
    for (int i = 0; i < 16; i++) {
        float4 v = p[threadIdx.x + i * 256];
        s += v.x + v.y + v.z + v.w;
    }
    __shared__ float sd[256];
    sd[threadIdx.x] = s;
    __syncthreads();
    for (int off = 128; off > 0; off >>= 1) {
        if (threadIdx.x < off) sd[threadIdx.x] += sd[threadIdx.x + off];
        __syncthreads();
    }
    if (threadIdx.x == 0) g_pooled[bc] = sd[0] * (1.f / (float)NPIX);
}

// ---------------- 2) attention ----------------
__global__ void att_kernel(const float* __restrict__ ksm_w) {
    int tid = threadIdx.x;
    int b = tid >> 6;
    int k = tid & 63;
    float s = 0.f;
    #pragma unroll 8
    for (int c = 0; c < NCIN; c++)
        s += g_pooled[b * NCIN + c] * ksm_w[k * NCIN + c];
    float sig = 1.f / (1.f + expf(-s));
    __shared__ float sl[1024];
    sl[tid] = sig;
    __syncthreads();
    float mx = -1e30f;
    #pragma unroll 8
    for (int i = 0; i < NK; i++) mx = fmaxf(mx, sl[b * NK + i]);
    float sum = 0.f;
    #pragma unroll 8
    for (int i = 0; i < NK; i++) sum += expf(sl[b * NK + i] - mx);
    g_att[tid] = expf(sig - mx) / sum;
}

// ---------------- 3) aggregate over kernel bank ----------------
__global__ void __launch_bounds__(256) agg_kernel(const float* __restrict__ dft) {
    __shared__ float s_att[NB * NK];
    int tid = threadIdx.x;
    #pragma unroll
    for (int i = 0; i < 4; i++) s_att[tid + i * 256] = g_att[tid + i * 256];
    __syncthreads();

    int base = blockIdx.x * 1024 + tid;
    float acc[16][4];
    #pragma unroll
    for (int b = 0; b < 16; b++)
        #pragma unroll
        for (int c = 0; c < 4; c++) acc[b][c] = 0.f;

    for (int k = 0; k < NK; k++) {
        const float* row = dft + (size_t)k * KCOLS + base;
        float w0 = row[0], w1 = row[256], w2 = row[512], w3 = row[768];
        #pragma unroll
        for (int b = 0; b < 16; b++) {
            float a = s_att[b * NK + k];
            acc[b][0] = fmaf(a, w0, acc[b][0]);
            acc[b][1] = fmaf(a, w1, acc[b][1]);
            acc[b][2] = fmaf(a, w2, acc[b][2]);
            acc[b][3] = fmaf(a, w3, acc[b][3]);
        }
    }
    #pragma unroll
    for (int b = 0; b < 16; b++)
        #pragma unroll
        for (int c = 0; c < 4; c++)
            g_agg[(size_t)b * KCOLS + base + c * 256] = acc[b][c];
}

// ---------------- 4) 3x3 ortho iFFT + clip + tf32 RN-round ----------------
__global__ void ifft_kernel() {
    int id = blockIdx.x * 256 + threadIdx.x;   // 0 .. 262143  (b, oc, ic)
    int b = id >> 14;
    int oi = id & 16383;
    const float* a = g_agg + (size_t)b * KCOLS + (size_t)oi * 18;
    float re[9], im[9];
    #pragma unroll
    for (int t = 0; t < 9; t++) { re[t] = a[2 * t]; im[t] = a[2 * t + 1]; }

    const float C3[3] = {1.f, -0.5f, -0.5f};
    const float S3[3] = {0.f, 0.86602540378443864676f, -0.86602540378443864676f};

    float* kout = g_kern + (size_t)id * 9;
    #pragma unroll
    for (int p = 0; p < 3; p++) {
        #pragma unroll
        for (int q = 0; q < 3; q++) {
            float s = 0.f;
            #pragma unroll
            for (int u = 0; u < 3; u++)
                #pragma unroll
                for (int v = 0; v < 3; v++) {
                    int m = (u * p + v * q) % 3;
                    s += re[u * 3 + v] * C3[m] - im[u * 3 + v] * S3[m];
                }
            s *= (1.f / 3.f);
            s = fminf(10.f, fmaxf(-10.f, s));
            uint32_t rb;
            asm("cvt.rna.tf32.f32 %0, %1;" : "=r"(rb) : "f"(s));   // RN tf32 (zero-mean error)
            kout[p * 3 + q] = __uint_as_float(rb);
        }
    }
}

// ---------------- 5) conv: tf32 mma.sync implicit GEMM ----------------
// CTA: b=blockIdx.y, y=blockIdx.x. M=128 oc, N=128 px, K=1152, BK=16, double-buffered.
// 8 warps: (wid&3) -> M group of 32, (wid>>2) -> N group of 64. Warp tile 32x64.
__global__ void __launch_bounds__(256, 2) conv_kernel(
    const float* __restrict__ x,
    const float* __restrict__ bias,
    const float* __restrict__ fbm,
    float* __restrict__ out) {

    __shared__ float As[2 * ASZ];   // [oc][k] rows padded to 20 floats
    __shared__ float Bs[2 * BSZ];   // [px][k] rows padded to 20 floats

    const int b = blockIdx.y;
    const int y = blockIdx.x;
    const int tid = threadIdx.x;
    const int lane = tid & 31;
    const int wid = tid >> 5;
    const int g = lane >> 2;
    const int tig = lane & 3;
    const int mb = (wid & 3) * 32;
    const int nb = (wid >> 2) * 64;

    const float* xb = x + (size_t)b * NCIN * NPIX;
    const float* kb = g_kern + (size_t)b * NCOUT * KSIZE;

    // A cp.async: 512 16B chunks; thread handles chunks tid and tid+256
    const int a_oc0 = tid >> 2;
    const int a_kc = (tid & 3) * 4;
    const uint32_t as_u = smem_u32(As);
    const uint32_t bs_u = smem_u32(Bs);
    const uint32_t a_d0 = as_u + (uint32_t)(a_oc0 * APAD + a_kc) * 4;
    const uint32_t a_d1 = as_u + (uint32_t)((a_oc0 + 64) * APAD + a_kc) * 4;

    // B gather: thread covers px = tid&127, k = (tid>>7)*8 + i (i=0..7)
    const int b_px = tid & 127;
    const int b_kh = tid >> 7;

    // ldmatrix addresses (lane-dependent rows)
    const int lrow = (lane & 7) + ((lane >> 4) << 3);
    const int lhalf = ((lane >> 3) & 1) * 4;
    uint32_t a_ld[2], b_ld[4];
    #pragma unroll
    for (int mt = 0; mt < 2; mt++)
        a_ld[mt] = as_u + (uint32_t)((mb + mt * 16 + lrow) * APAD + lhalf) * 4;
    #pragma unroll
    for (int np = 0; np < 4; np++)
        b_ld[np] = bs_u + (uint32_t)((nb + np * 16 + lrow) * BPAD + lhalf) * 4;

    float acc[2][8][4];
    #pragma unroll
    for (int mt = 0; mt < 2; mt++)
        #pragma unroll
        for (int nt = 0; nt < 8; nt++)
            #pragma unroll
            for (int i = 0; i < 4; i++) acc[mt][nt][i] = 0.f;

    float bv[8];

    #define LOADB(cc)                                                      \
    {                                                                      \
        int kk0 = (cc) * 16 + b_kh * 8;                                    \
        _Pragma("unroll")                                                  \
        for (int i = 0; i < 8; i++) {                                      \
            int kk = kk0 + i;                                              \
            int ic = kk / 9;                                               \
            int t = kk - ic * 9;                                           \
            int dy = t / 3;                                                \
            int dx = t - dy * 3;                                           \
            int yy = y + dy - 1;                                           \
            int gx = b_px + dx - 1;                                        \
            float v = 0.f;                                                 \
            if ((unsigned)yy < 128u && (unsigned)gx < 128u)                \
                v = xb[((size_t)ic << 14) + (yy << 7) + gx];               \
            bv[i] = v;                                                     \
        }                                                                  \
    }

    #define LOADA(cc, bufsel)                                              \
    {                                                                      \
        const float* s0 = kb + (size_t)a_oc0 * KSIZE + (cc) * 16 + a_kc;   \
        const float* s1 = s0 + 64 * KSIZE;                                 \
        uint32_t off = (uint32_t)(bufsel) * ASZ * 4;                       \
        CP_A16(a_d0 + off, s0);                                            \
        CP_A16(a_d1 + off, s1);                                            \
    }

    #define STSB(bufsel)                                                   \
    {                                                                      \
        uint32_t r[8];                                                     \
        _Pragma("unroll")                                                  \
        for (int i = 0; i < 8; i++)                                        \
            asm("cvt.rna.tf32.f32 %0, %1;" : "=r"(r[i]) : "f"(bv[i]));     \
        float* dst = Bs + (bufsel) * BSZ + b_px * BPAD + b_kh * 8;         \
        *(uint4*)(dst) = *(uint4*)(r);                                     \
        *(uint4*)(dst + 4) = *(uint4*)(r + 4);                             \
    }

    #define COMPUTE(bufsel)                                                \
    {                                                                      \
        uint32_t ao = (uint32_t)(bufsel) * ASZ * 4;                        \
        uint32_t bo = (uint32_t)(bufsel) * BSZ * 4;                        \
        _Pragma("unroll")                                                  \
        for (int ks = 0; ks < 2; ks++) {                                   \
            uint32_t qa0[4], qa1[4], qb[4][4];                             \
            LDM(qa0, a_ld[0] + ao + ks * 32);                              \
            LDM(qa1, a_ld[1] + ao + ks * 32);                              \
            LDM(qb[0], b_ld[0] + bo + ks * 32);                            \
            LDM(qb[1], b_ld[1] + bo + ks * 32);                            \
            LDM(qb[2], b_ld[2] + bo + ks * 32);                            \
            LDM(qb[3], b_ld[3] + bo + ks * 32);                            \
            _Pragma("unroll")                                              \
            for (int nt = 0; nt < 8; nt++) {                               \
                uint32_t b0 = qb[nt >> 1][(nt & 1) * 2];                   \
                uint32_t b1 = qb[nt >> 1][(nt & 1) * 2 + 1];               \
                MMA(acc[0][nt], qa0, b0, b1);                              \
                MMA(acc[1][nt], qa1, b0, b1);                              \
            }                                                              \
        }                                                                  \
    }

    // ---- prologue: stage 0 ----
    LOADB(0);
    LOADA(0, 0);
    CP_COMMIT();
    STSB(0);
    CP_WAIT0();
    __syncthreads();

    // ---- main loop ----
    for (int c = 0; c < NSTAGE; c++) {
        int buf = c & 1;
        if (c < NSTAGE - 1) {
            LOADB(c + 1);
            LOADA(c + 1, buf ^ 1);
            CP_COMMIT();
        }
        COMPUTE(buf);
        if (c < NSTAGE - 1) STSB(buf ^ 1);
        CP_WAIT0();
        __syncthreads();
    }

    // ---- epilogue: (acc + bias) * fbm -> gmem ----
    #pragma unroll
    for (int mt = 0; mt < 2; mt++) {
        int oc0 = mb + mt * 16 + g;
        int oc1 = oc0 + 8;
        float bi0 = bias[oc0], sc0 = fbm[oc0];
        float bi1 = bias[oc1], sc1 = fbm[oc1];
        float* o0 = out + (((size_t)(b * NCOUT + oc0)) * NHW + y) * NHW;
        float* o1 = out + (((size_t)(b * NCOUT + oc1)) * NHW + y) * NHW;
        #pragma unroll
        for (int nt = 0; nt < 8; nt++) {
            int px = nb + nt * 8 + tig * 2;
            float2 v0, v1;
            v0.x = (acc[mt][nt][0] + bi0) * sc0;
            v0.y = (acc[mt][nt][1] + bi0) * sc0;
            v1.x = (acc[mt][nt][2] + bi1) * sc1;
            v1.y = (acc[mt][nt][3] + bi1) * sc1;
            *(float2*)(o0 + px) = v0;
            *(float2*)(o1 + px) = v1;
        }
    }
}

// ---------------- launch ----------------
extern "C" void kernel_launch(void* const* d_in, const int* in_sizes, int n_in,
                              void* d_out, int out_size) {
    const float* x    = (const float*)d_in[0];
    const float* dft  = (const float*)d_in[1];
    const float* ksm  = (const float*)d_in[2];
    const float* bias = (const float*)d_in[3];
    const float* fbm  = (const float*)d_in[4];
    float* out = (float*)d_out;

    pool_kernel<<<NB * NCIN, 256>>>(x);
    att_kernel<<<1, 1024>>>(ksm);
    agg_kernel<<<KCOLS / 1024, 256>>>(dft);
    ifft_kernel<<<(NB * NCOUT * NCIN) / 256, 256>>>();
    conv_kernel<<<dim3(NHW, NB), 256>>>(x, bias, fbm, out);
}

// round 7
// speedup vs baseline: 2.5208x; 1.0021x over previous
#include <cuda_runtime.h>
#include <cstdint>

// ---------------- problem constants ----------------
#define NB    16
#define NCIN  128
#define NCOUT 128
#define NHW   128
#define NPIX  16384
#define NK    64
#define KCOLS 294912
#define KSIZE 1152
#define NSTAGE 72           // KSIZE / 16
#define APAD  20
#define BPAD  20
#define ASZ   (128 * APAD)  // floats per A stage (2560)
#define BSZ   (128 * BPAD)  // floats per B stage (2560)

// ---------------- scratch ----------------
__device__ float g_pooled[NB * NCIN];
__device__ float g_att[NB * NK];
__device__ float g_agg[(size_t)NB * KCOLS];            // 18.9 MB
__device__ float g_kern[(size_t)NB * NCOUT * KSIZE];   // 9.4 MB, tf32-rounded

// ---------------- helpers ----------------
__device__ __forceinline__ uint32_t smem_u32(const void* p) {
    uint32_t a;
    asm("{ .reg .u64 t; cvta.to.shared.u64 t, %1; cvt.u32.u64 %0, t; }" : "=r"(a) : "l"(p));
    return a;
}
#define CP_A16(dst, src) \
    asm volatile("cp.async.ca.shared.global [%0], [%1], 16;" :: "r"(dst), "l"(src) : "memory")
#define CP_COMMIT() asm volatile("cp.async.commit_group;" ::: "memory")
#define CP_WAIT0()  asm volatile("cp.async.wait_group 0;" ::: "memory")
#define CP_WAIT1()  asm volatile("cp.async.wait_group 1;" ::: "memory")

#define LDM(q, addr) \
    asm volatile("ldmatrix.sync.aligned.m8n8.x4.shared.b16 {%0,%1,%2,%3}, [%4];" \
        : "=r"((q)[0]), "=r"((q)[1]), "=r"((q)[2]), "=r"((q)[3]) : "r"(addr))

// A-fragment register order from ldmatrix: q0=a0, q1=a2, q2=a1, q3=a3 -> pass {q0,q2,q1,q3}
#define MMA(C, qa, b0, b1) \
    asm volatile("mma.sync.aligned.m16n8k8.row.col.f32.tf32.tf32.f32 " \
        "{%0,%1,%2,%3},{%4,%5,%6,%7},{%8,%9},{%0,%1,%2,%3};" \
        : "+f"((C)[0]), "+f"((C)[1]), "+f"((C)[2]), "+f"((C)[3]) \
        : "r"((qa)[0]), "r"((qa)[2]), "r"((qa)[1]), "r"((qa)[3]), "r"(b0), "r"(b1))

// ---------------- 1) global average pool ----------------
__global__ void pool_kernel(const float* __restrict__ x) {
    int bc = blockIdx.x;
    const float4* p = (const float4*)(x + (size_t)bc * NPIX);
    float s = 0.f;
    #pragma unroll
    for (int i = 0; i < 16; i++) {
        float4 v = p[threadIdx.x + i * 256];
        s += v.x + v.y + v.z + v.w;
    }
    __shared__ float sd[256];
    sd[threadIdx.x] = s;
    __syncthreads();
    for (int off = 128; off > 0; off >>= 1) {
        if (threadIdx.x < off) sd[threadIdx.x] += sd[threadIdx.x + off];
        __syncthreads();
    }
    if (threadIdx.x == 0) g_pooled[bc] = sd[0] * (1.f / (float)NPIX);
}

// ---------------- 2) attention ----------------
__global__ void att_kernel(const float* __restrict__ ksm_w) {
    int tid = threadIdx.x;
    int b = tid >> 6;
    int k = tid & 63;
    float s = 0.f;
    #pragma unroll 8
    for (int c = 0; c < NCIN; c++)
        s += g_pooled[b * NCIN + c] * ksm_w[k * NCIN + c];
    float sig = 1.f / (1.f + expf(-s));
    __shared__ float sl[1024];
    sl[tid] = sig;
    __syncthreads();
    float mx = -1e30f;
    #pragma unroll 8
    for (int i = 0; i < NK; i++) mx = fmaxf(mx, sl[b * NK + i]);
    float sum = 0.f;
    #pragma unroll 8
    for (int i = 0; i < NK; i++) sum += expf(sl[b * NK + i] - mx);
    g_att[tid] = expf(sig - mx) / sum;
}

// ---------------- 3) aggregate over kernel bank ----------------
__global__ void __launch_bounds__(256) agg_kernel(const float* __restrict__ dft) {
    __shared__ float s_att[NB * NK];
    int tid = threadIdx.x;
    #pragma unroll
    for (int i = 0; i < 4; i++) s_att[tid + i * 256] = g_att[tid + i * 256];
    __syncthreads();

    int base = blockIdx.x * 1024 + tid;
    float acc[16][4];
    #pragma unroll
    for (int b = 0; b < 16; b++)
        #pragma unroll
        for (int c = 0; c < 4; c++) acc[b][c] = 0.f;

    for (int k = 0; k < NK; k++) {
        const float* row = dft + (size_t)k * KCOLS + base;
        float w0 = row[0], w1 = row[256], w2 = row[512], w3 = row[768];
        #pragma unroll
        for (int b = 0; b < 16; b++) {
            float a = s_att[b * NK + k];
            acc[b][0] = fmaf(a, w0, acc[b][0]);
            acc[b][1] = fmaf(a, w1, acc[b][1]);
            acc[b][2] = fmaf(a, w2, acc[b][2]);
            acc[b][3] = fmaf(a, w3, acc[b][3]);
        }
    }
    #pragma unroll
    for (int b = 0; b < 16; b++)
        #pragma unroll
        for (int c = 0; c < 4; c++)
            g_agg[(size_t)b * KCOLS + base + c * 256] = acc[b][c];
}

// ---------------- 4) 3x3 ortho iFFT + clip + tf32 RN-round ----------------
__global__ void ifft_kernel() {
    int id = blockIdx.x * 256 + threadIdx.x;   // (b, oc, ic)
    int b = id >> 14;
    int oi = id & 16383;
    const float* a = g_agg + (size_t)b * KCOLS + (size_t)oi * 18;
    float re[9], im[9];
    #pragma unroll
    for (int t = 0; t < 9; t++) { re[t] = a[2 * t]; im[t] = a[2 * t + 1]; }

    const float C3[3] = {1.f, -0.5f, -0.5f};
    const float S3[3] = {0.f, 0.86602540378443864676f, -0.86602540378443864676f};

    float* kout = g_kern + (size_t)id * 9;
    #pragma unroll
    for (int p = 0; p < 3; p++) {
        #pragma unroll
        for (int q = 0; q < 3; q++) {
            float s = 0.f;
            #pragma unroll
            for (int u = 0; u < 3; u++)
                #pragma unroll
                for (int v = 0; v < 3; v++) {
                    int m = (u * p + v * q) % 3;
                    s += re[u * 3 + v] * C3[m] - im[u * 3 + v] * S3[m];
                }
            s *= (1.f / 3.f);
            s = fminf(10.f, fmaxf(-10.f, s));
            uint32_t rb;
            asm("cvt.rna.tf32.f32 %0, %1;" : "=r"(rb) : "f"(s));
            kout[p * 3 + q] = __uint_as_float(rb);
        }
    }
}

// ---------------- 5) conv: tf32 mma.sync implicit GEMM ----------------
// CTA: b=blockIdx.y, y=blockIdx.x. M=128 oc, N=128 px, K=1152, BK=16.
// 3-way circular smem buffers, cp.async wait_group 1, one barrier per stage.
// 8 warps: (wid&3)->M group of 32, (wid>>2)->N group of 64.
__global__ void __launch_bounds__(256, 2) conv_kernel(
    const float* __restrict__ x,
    const float* __restrict__ bias,
    const float* __restrict__ fbm,
    float* __restrict__ out) {

    extern __shared__ float sms[];
    float* const As = sms;              // 3 * ASZ
    float* const Bs = sms + 3 * ASZ;    // 3 * BSZ

    const int b = blockIdx.y;
    const int y = blockIdx.x;
    const int tid = threadIdx.x;
    const int lane = tid & 31;
    const int wid = tid >> 5;
    const int g = lane >> 2;
    const int tig = lane & 3;
    const int mb = (wid & 3) * 32;
    const int nb = (wid >> 2) * 64;

    const float* xb = x + (size_t)b * NCIN * NPIX;
    const float* kb = g_kern + (size_t)b * NCOUT * KSIZE;

    // A cp.async mapping: 512 16B chunks per stage; thread covers 2
    const int a_oc0 = tid >> 2;
    const int a_kc = (tid & 3) * 4;
    const uint32_t as_u = smem_u32(As);
    const uint32_t bs_u = smem_u32(Bs);
    const uint32_t a_d0 = as_u + (uint32_t)(a_oc0 * APAD + a_kc) * 4;
    const uint32_t a_d1 = as_u + (uint32_t)((a_oc0 + 64) * APAD + a_kc) * 4;

    // B gather mapping: px = tid&127, k-half = tid>>7
    const int b_px = tid & 127;
    const int b_kh = tid >> 7;

    // ldmatrix base addresses (mt/np offsets folded as immediates)
    const int lrow = (lane & 7) + ((lane >> 4) << 3);
    const int lhalf = ((lane >> 3) & 1) * 4;
    const uint32_t a_base = as_u + (uint32_t)((mb + lrow) * APAD + lhalf) * 4;
    const uint32_t b_base = bs_u + (uint32_t)((nb + lrow) * BPAD + lhalf) * 4;

    float acc[2][8][4];
    #pragma unroll
    for (int mt = 0; mt < 2; mt++)
        #pragma unroll
        for (int nt = 0; nt < 8; nt++)
            #pragma unroll
            for (int i = 0; i < 4; i++) acc[mt][nt][i] = 0.f;

    float bv[8];

    #define LOADB(cc)                                                      \
    {                                                                      \
        int kk0 = (cc) * 16 + b_kh * 8;                                    \
        _Pragma("unroll")                                                  \
        for (int i = 0; i < 8; i++) {                                      \
            int kk = kk0 + i;                                              \
            int ic = kk / 9;                                               \
            int t = kk - ic * 9;                                           \
            int dy = t / 3;                                                \
            int dx = t - dy * 3;                                           \
            int yy = y + dy - 1;                                           \
            int gx = b_px + dx - 1;                                        \
            float v = 0.f;                                                 \
            if ((unsigned)yy < 128u && (unsigned)gx < 128u)                \
                v = xb[((size_t)ic << 14) + (yy << 7) + gx];               \
            bv[i] = v;                                                     \
        }                                                                  \
    }

    #define LOADA(cc, bufsel)                                              \
    {                                                                      \
        const float* s0 = kb + (size_t)a_oc0 * KSIZE + (cc) * 16 + a_kc;   \
        const float* s1 = s0 + 64 * KSIZE;                                 \
        uint32_t off = (uint32_t)(bufsel) * (ASZ * 4);                     \
        CP_A16(a_d0 + off, s0);                                            \
        CP_A16(a_d1 + off, s1);                                            \
    }

    #define STSB(bufsel)                                                   \
    {                                                                      \
        uint32_t r[8];                                                     \
        _Pragma("unroll")                                                  \
        for (int i = 0; i < 8; i++)                                        \
            asm("cvt.rna.tf32.f32 %0, %1;" : "=r"(r[i]) : "f"(bv[i]));     \
        float* dst = Bs + (bufsel) * BSZ + b_px * BPAD + b_kh * 8;         \
        *(uint4*)(dst) = *(uint4*)(r);                                     \
        *(uint4*)(dst + 4) = *(uint4*)(r + 4);                             \
    }

    #define COMPUTE(bufsel)                                                \
    {                                                                      \
        uint32_t ao = (uint32_t)(bufsel) * (ASZ * 4);                      \
        uint32_t bo = (uint32_t)(bufsel) * (BSZ * 4);                      \
        _Pragma("unroll")                                                  \
        for (int ks = 0; ks < 2; ks++) {                                   \
            uint32_t qa0[4], qa1[4], qb[2][4];                             \
            LDM(qa0, a_base + ao + ks * 32);                               \
            LDM(qa1, a_base + ao + ks * 32 + 16 * APAD * 4);               \
            LDM(qb[0], b_base + bo + ks * 32);                             \
            _Pragma("unroll")                                              \
            for (int np = 0; np < 4; np++) {                               \
                if (np < 3)                                                \
                    LDM(qb[(np + 1) & 1],                                  \
                        b_base + bo + ks * 32 + (np + 1) * (16 * BPAD * 4)); \
                uint32_t b0 = qb[np & 1][0], b1 = qb[np & 1][1];           \
                uint32_t b2 = qb[np & 1][2], b3 = qb[np & 1][3];           \
                MMA(acc[0][2 * np], qa0, b0, b1);                          \
                MMA(acc[1][2 * np], qa1, b0, b1);                          \
                MMA(acc[0][2 * np + 1], qa0, b2, b3);                      \
                MMA(acc[1][2 * np + 1], qa1, b2, b3);                      \
            }                                                              \
        }                                                                  \
    }

    // ---- prologue: stage 0 ----
    LOADB(0);
    LOADA(0, 0);
    CP_COMMIT();
    STSB(0);

    // ---- main loop: 3-way circular buffers, wait_group 1 ----
    int buf = 0;
    for (int c = 0; c < NSTAGE; c++) {
        int bufn = (buf == 2) ? 0 : buf + 1;
        if (c < NSTAGE - 1) {
            LOADB(c + 1);
            LOADA(c + 1, bufn);
            CP_COMMIT();
            CP_WAIT1();          // own group c complete (group c+1 stays in flight)
        } else {
            CP_WAIT0();
        }
        __syncthreads();         // everyone's stage-c A + B visible; safe vs overwrites
        COMPUTE(buf);
        if (c < NSTAGE - 1) STSB(bufn);
        buf = bufn;
    }

    // ---- epilogue: (acc + bias) * fbm -> gmem ----
    #pragma unroll
    for (int mt = 0; mt < 2; mt++) {
        int oc0 = mb + mt * 16 + g;
        int oc1 = oc0 + 8;
        float bi0 = bias[oc0], sc0 = fbm[oc0];
        float bi1 = bias[oc1], sc1 = fbm[oc1];
        float* o0 = out + (((size_t)(b * NCOUT + oc0)) * NHW + y) * NHW;
        float* o1 = out + (((size_t)(b * NCOUT + oc1)) * NHW + y) * NHW;
        #pragma unroll
        for (int nt = 0; nt < 8; nt++) {
            int px = nb + nt * 8 + tig * 2;
            float2 v0, v1;
            v0.x = (acc[mt][nt][0] + bi0) * sc0;
            v0.y = (acc[mt][nt][1] + bi0) * sc0;
            v1.x = (acc[mt][nt][2] + bi1) * sc1;
            v1.y = (acc[mt][nt][3] + bi1) * sc1;
            *(float2*)(o0 + px) = v0;
            *(float2*)(o1 + px) = v1;
        }
    }
}

// ---------------- launch ----------------
extern "C" void kernel_launch(void* const* d_in, const int* in_sizes, int n_in,
                              void* d_out, int out_size) {
    const float* x    = (const float*)d_in[0];
    const float* dft  = (const float*)d_in[1];
    const float* ksm  = (const float*)d_in[2];
    const float* bias = (const float*)d_in[3];
    const float* fbm  = (const float*)d_in[4];
    float* out = (float*)d_out;

    pool_kernel<<<NB * NCIN, 256>>>(x);
    att_kernel<<<1, 1024>>>(ksm);
    agg_kernel<<<KCOLS / 1024, 256>>>(dft);
    ifft_kernel<<<(NB * NCOUT * NCIN) / 256, 256>>>();

    const int dyn = 3 * (ASZ + BSZ) * 4;   // 61,440 bytes
    cudaFuncSetAttribute(conv_kernel, cudaFuncAttributeMaxDynamicSharedMemorySize, dyn);
    conv_kernel<<<dim3(NHW, NB), 256, dyn>>>(x, bias, fbm, out);
}

// round 8
// speedup vs baseline: 3.4204x; 1.3569x over previous
#include <cuda_runtime.h>
#include <cuda_fp16.h>
#include <cstdint>

// ---------------- problem constants ----------------
#define NB    16
#define NCIN  128
#define NCOUT 128
#define NHW   128
#define NPIX  16384
#define NK    64
#define KCOLS 294912
#define KSIZE 1152
#define NSTAGE 72           // KSIZE / 16
#define RPADH 24            // halfs per smem row (48 B stride, conflict-free ldmatrix)
#define ASZH  (128 * RPADH) // halfs per A stage (3072)
#define BSZH  (128 * RPADH) // halfs per B stage (3072)

// ---------------- scratch ----------------
__device__ float  g_pooled[NB * NCIN];
__device__ float  g_att[NB * NK];
__device__ float  g_agg[(size_t)NB * KCOLS];             // 18.9 MB
__device__ __half g_kern[(size_t)NB * NCOUT * KSIZE];    // 4.7 MB, fp16 kernels

// ---------------- helpers ----------------
__device__ __forceinline__ uint32_t smem_u32(const void* p) {
    uint32_t a;
    asm("{ .reg .u64 t; cvta.to.shared.u64 t, %1; cvt.u32.u64 %0, t; }" : "=r"(a) : "l"(p));
    return a;
}
#define CP_A16(dst, src) \
    asm volatile("cp.async.ca.shared.global [%0], [%1], 16;" :: "r"(dst), "l"(src) : "memory")
#define CP_COMMIT() asm volatile("cp.async.commit_group;" ::: "memory")
#define CP_WAIT0()  asm volatile("cp.async.wait_group 0;" ::: "memory")
#define CP_WAIT1()  asm volatile("cp.async.wait_group 1;" ::: "memory")

#define LDM(q, addr) \
    asm volatile("ldmatrix.sync.aligned.m8n8.x4.shared.b16 {%0,%1,%2,%3}, [%4];" \
        : "=r"((q)[0]), "=r"((q)[1]), "=r"((q)[2]), "=r"((q)[3]) : "r"(addr))

// fp16 MMA, fp32 accumulate. A fragment {a0,a1,a2,a3} in natural ldmatrix order.
#define MMAH(C, qa, b0, b1) \
    asm volatile("mma.sync.aligned.m16n8k16.row.col.f32.f16.f16.f32 " \
        "{%0,%1,%2,%3},{%4,%5,%6,%7},{%8,%9},{%0,%1,%2,%3};" \
        : "+f"((C)[0]), "+f"((C)[1]), "+f"((C)[2]), "+f"((C)[3]) \
        : "r"((qa)[0]), "r"((qa)[1]), "r"((qa)[2]), "r"((qa)[3]), "r"(b0), "r"(b1))

// ---------------- 1) global average pool ----------------
__global__ void pool_kernel(const float* __restrict__ x) {
    int bc = blockIdx.x;
    const float4* p = (const float4*)(x + (size_t)bc * NPIX);
    float s = 0.f;
    #pragma unroll
    for (int i = 0; i < 16; i++) {
        float4 v = p[threadIdx.x + i * 256];
        s += v.x + v.y + v.z + v.w;
    }
    __shared__ float sd[256];
    sd[threadIdx.x] = s;
    __syncthreads();
    for (int off = 128; off > 0; off >>= 1) {
        if (threadIdx.x < off) sd[threadIdx.x] += sd[threadIdx.x + off];
        __syncthreads();
    }
    if (threadIdx.x == 0) g_pooled[bc] = sd[0] * (1.f / (float)NPIX);
}

// ---------------- 2) attention ----------------
__global__ void att_kernel(const float* __restrict__ ksm_w) {
    int tid = threadIdx.x;
    int b = tid >> 6;
    int k = tid & 63;
    float s = 0.f;
    #pragma unroll 8
    for (int c = 0; c < NCIN; c++)
        s += g_pooled[b * NCIN + c] * ksm_w[k * NCIN + c];
    float sig = 1.f / (1.f + expf(-s));
    __shared__ float sl[1024];
    sl[tid] = sig;
    __syncthreads();
    float mx = -1e30f;
    #pragma unroll 8
    for (int i = 0; i < NK; i++) mx = fmaxf(mx, sl[b * NK + i]);
    float sum = 0.f;
    #pragma unroll 8
    for (int i = 0; i < NK; i++) sum += expf(sl[b * NK + i] - mx);
    g_att[tid] = expf(sig - mx) / sum;
}

// ---------------- 3) aggregate over kernel bank ----------------
__global__ void __launch_bounds__(256) agg_kernel(const float* __restrict__ dft) {
    __shared__ float s_att[NB * NK];
    int tid = threadIdx.x;
    #pragma unroll
    for (int i = 0; i < 4; i++) s_att[tid + i * 256] = g_att[tid + i * 256];
    __syncthreads();

    int base = blockIdx.x * 1024 + tid;
    float acc[16][4];
    #pragma unroll
    for (int b = 0; b < 16; b++)
        #pragma unroll
        for (int c = 0; c < 4; c++) acc[b][c] = 0.f;

    for (int k = 0; k < NK; k++) {
        const float* row = dft + (size_t)k * KCOLS + base;
        float w0 = row[0], w1 = row[256], w2 = row[512], w3 = row[768];
        #pragma unroll
        for (int b = 0; b < 16; b++) {
            float a = s_att[b * NK + k];
            acc[b][0] = fmaf(a, w0, acc[b][0]);
            acc[b][1] = fmaf(a, w1, acc[b][1]);
            acc[b][2] = fmaf(a, w2, acc[b][2]);
            acc[b][3] = fmaf(a, w3, acc[b][3]);
        }
    }
    #pragma unroll
    for (int b = 0; b < 16; b++)
        #pragma unroll
        for (int c = 0; c < 4; c++)
            g_agg[(size_t)b * KCOLS + base + c * 256] = acc[b][c];
}

// ---------------- 4) 3x3 ortho iFFT + clip -> fp16 kernels ----------------
__global__ void ifft_kernel() {
    int id = blockIdx.x * 256 + threadIdx.x;   // (b, oc, ic)
    int b = id >> 14;
    int oi = id & 16383;
    const float* a = g_agg + (size_t)b * KCOLS + (size_t)oi * 18;
    float re[9], im[9];
    #pragma unroll
    for (int t = 0; t < 9; t++) { re[t] = a[2 * t]; im[t] = a[2 * t + 1]; }

    const float C3[3] = {1.f, -0.5f, -0.5f};
    const float S3[3] = {0.f, 0.86602540378443864676f, -0.86602540378443864676f};

    __half* kout = g_kern + (size_t)id * 9;
    #pragma unroll
    for (int p = 0; p < 3; p++) {
        #pragma unroll
        for (int q = 0; q < 3; q++) {
            float s = 0.f;
            #pragma unroll
            for (int u = 0; u < 3; u++)
                #pragma unroll
                for (int v = 0; v < 3; v++) {
                    int m = (u * p + v * q) % 3;
                    s += re[u * 3 + v] * C3[m] - im[u * 3 + v] * S3[m];
                }
            s *= (1.f / 3.f);
            s = fminf(10.f, fmaxf(-10.f, s));
            kout[p * 3 + q] = __float2half_rn(s);
        }
    }
}

// ---------------- 5) conv: fp16 mma.sync m16n8k16 implicit GEMM ----------------
// CTA: b=blockIdx.y, y=blockIdx.x. M=128 oc, N=128 px, K=1152, BK=16.
// 3-way circular smem buffers, cp.async wait_group 1, one barrier per stage.
// 8 warps: (wid&3)->M group of 32, (wid>>2)->N group of 64.
__global__ void __launch_bounds__(256, 2) conv_kernel(
    const float* __restrict__ x,
    const float* __restrict__ bias,
    const float* __restrict__ fbm,
    float* __restrict__ out) {

    __shared__ __align__(16) __half As[3 * ASZH];
    __shared__ __align__(16) __half Bs[3 * BSZH];

    const int b = blockIdx.y;
    const int y = blockIdx.x;
    const int tid = threadIdx.x;
    const int lane = tid & 31;
    const int wid = tid >> 5;
    const int g = lane >> 2;
    const int tig = lane & 3;
    const int mb = (wid & 3) * 32;
    const int nb = (wid >> 2) * 64;

    const float* xb = x + (size_t)b * NCIN * NPIX;
    const __half* kb = g_kern + (size_t)b * NCOUT * KSIZE;

    // A cp.async mapping: 256 16B chunks per stage (one per thread)
    const int a_oc = tid >> 1;
    const int a_kc = (tid & 1) * 8;          // halfs
    const uint32_t as_u = smem_u32(As);
    const uint32_t bs_u = smem_u32(Bs);
    const uint32_t a_dst = as_u + (uint32_t)(a_oc * RPADH + a_kc) * 2;

    // B gather mapping: px = tid&127, k-half = tid>>7
    const int b_px = tid & 127;
    const int b_kh = tid >> 7;

    // ldmatrix lane addressing
    // A (x4): j0=m0-7/k0-7, j1=m8-15/k0-7, j2=m0-7/k8-15, j3=m8-15/k8-15 -> natural a0..a3
    const int a_row = (lane & 7) + (((lane >> 3) & 1) << 3);
    const int a_kh8 = (lane >> 4) * 8;
    // B (x4): j0=n0-7/k0-7, j1=n0-7/k8-15, j2=n8-15/k0-7, j3=n8-15/k8-15
    const int b_row = (lane & 7) + ((lane >> 4) << 3);
    const int b_kh8 = ((lane >> 3) & 1) * 8;
    const uint32_t a_base = as_u + (uint32_t)((mb + a_row) * RPADH + a_kh8) * 2;
    const uint32_t b_base = bs_u + (uint32_t)((nb + b_row) * RPADH + b_kh8) * 2;

    float acc[2][8][4];
    #pragma unroll
    for (int mt = 0; mt < 2; mt++)
        #pragma unroll
        for (int nt = 0; nt < 8; nt++)
            #pragma unroll
            for (int i = 0; i < 4; i++) acc[mt][nt][i] = 0.f;

    float bv[8];

    #define LOADB(cc)                                                      \
    {                                                                      \
        int kk0 = (cc) * 16 + b_kh * 8;                                    \
        _Pragma("unroll")                                                  \
        for (int i = 0; i < 8; i++) {                                      \
            int kk = kk0 + i;                                              \
            int ic = kk / 9;                                               \
            int t = kk - ic * 9;                                           \
            int dy = t / 3;                                                \
            int dx = t - dy * 3;                                           \
            int yy = y + dy - 1;                                           \
            int gx = b_px + dx - 1;                                        \
            float v = 0.f;                                                 \
            if ((unsigned)yy < 128u && (unsigned)gx < 128u)                \
                v = xb[((size_t)ic << 14) + (yy << 7) + gx];               \
            bv[i] = v;                                                     \
        }                                                                  \
    }

    #define LOADA(cc, bufsel)                                              \
    {                                                                      \
        const __half* s0 = kb + (size_t)a_oc * KSIZE + (cc) * 16 + a_kc;   \
        CP_A16(a_dst + (uint32_t)(bufsel) * (ASZH * 2), s0);               \
    }

    #define STSB(bufsel)                                                   \
    {                                                                      \
        uint32_t r[4];                                                     \
        _Pragma("unroll")                                                  \
        for (int i = 0; i < 4; i++)                                        \
            asm("cvt.rn.f16x2.f32 %0, %1, %2;"                             \
                : "=r"(r[i]) : "f"(bv[2 * i + 1]), "f"(bv[2 * i]));        \
        __half* dst = Bs + (bufsel) * BSZH + b_px * RPADH + b_kh * 8;      \
        *(uint4*)(dst) = *(uint4*)(r);                                     \
    }

    #define COMPUTE(bufsel)                                                \
    {                                                                      \
        uint32_t ao = (uint32_t)(bufsel) * (ASZH * 2);                     \
        uint32_t bo = (uint32_t)(bufsel) * (BSZH * 2);                     \
        uint32_t qa0[4], qa1[4];                                           \
        LDM(qa0, a_base + ao);                                             \
        LDM(qa1, a_base + ao + 16 * RPADH * 2);                            \
        _Pragma("unroll")                                                  \
        for (int np = 0; np < 4; np++) {                                   \
            uint32_t qb[4];                                                \
            LDM(qb, b_base + bo + np * (16 * RPADH * 2));                  \
            MMAH(acc[0][2 * np], qa0, qb[0], qb[1]);                       \
            MMAH(acc[1][2 * np], qa1, qb[0], qb[1]);                       \
            MMAH(acc[0][2 * np + 1], qa0, qb[2], qb[3]);                   \
            MMAH(acc[1][2 * np + 1], qa1, qb[2], qb[3]);                   \
        }                                                                  \
    }

    // ---- prologue: stage 0 ----
    LOADB(0);
    LOADA(0, 0);
    CP_COMMIT();
    STSB(0);

    // ---- main loop: 3-way circular buffers, wait_group 1 ----
    int buf = 0;
    for (int c = 0; c < NSTAGE; c++) {
        int bufn = (buf == 2) ? 0 : buf + 1;
        if (c < NSTAGE - 1) {
            LOADB(c + 1);
            LOADA(c + 1, bufn);
            CP_COMMIT();
            CP_WAIT1();          // own group c complete (group c+1 stays in flight)
        } else {
            CP_WAIT0();
        }
        __syncthreads();         // stage-c A + B visible to all; overwrite-safe
        COMPUTE(buf);
        if (c < NSTAGE - 1) STSB(bufn);
        buf = bufn;
    }

    // ---- epilogue: (acc + bias) * fbm -> gmem ----
    #pragma unroll
    for (int mt = 0; mt < 2; mt++) {
        int oc0 = mb + mt * 16 + g;
        int oc1 = oc0 + 8;
        float bi0 = bias[oc0], sc0 = fbm[oc0];
        float bi1 = bias[oc1], sc1 = fbm[oc1];
        float* o0 = out + (((size_t)(b * NCOUT + oc0)) * NHW + y) * NHW;
        float* o1 = out + (((size_t)(b * NCOUT + oc1)) * NHW + y) * NHW;
        #pragma unroll
        for (int nt = 0; nt < 8; nt++) {
            int px = nb + nt * 8 + tig * 2;
            float2 v0, v1;
            v0.x = (acc[mt][nt][0] + bi0) * sc0;
            v0.y = (acc[mt][nt][1] + bi0) * sc0;
            v1.x = (acc[mt][nt][2] + bi1) * sc1;
            v1.y = (acc[mt][nt][3] + bi1) * sc1;
            *(float2*)(o0 + px) = v0;
            *(float2*)(o1 + px) = v1;
        }
    }
}

// ---------------- launch ----------------
extern "C" void kernel_launch(void* const* d_in, const int* in_sizes, int n_in,
                              void* d_out, int out_size) {
    const float* x    = (const float*)d_in[0];
    const float* dft  = (const float*)d_in[1];
    const float* ksm  = (const float*)d_in[2];
    const float* bias = (const float*)d_in[3];
    const float* fbm  = (const float*)d_in[4];
    float* out = (float*)d_out;

    pool_kernel<<<NB * NCIN, 256>>>(x);
    att_kernel<<<1, 1024>>>(ksm);
    agg_kernel<<<KCOLS / 1024, 256>>>(dft);
    ifft_kernel<<<(NB * NCOUT * NCIN) / 256, 256>>>();
    conv_kernel<<<dim3(NHW, NB), 256>>>(x, bias, fbm, out);
}